// round 1
// baseline (speedup 1.0000x reference)
#include <cuda_runtime.h>
#include <cstdint>

#define N_TOK 131072
#define DIM   64
#define QSTG  8
#define KCB   1024

#define TM       128          // tokens per CTA
#define TKC      128          // codewords per SMEM chunk
#define NCHUNK   (KCB / TKC)  // 8
#define BPAD     66           // padded row stride (floats) for codeword tile
#define NTHREADS 256

#define SMEM_FLOATS (TM * DIM + TKC * BPAD + TKC)
#define SMEM_BYTES  (SMEM_FLOATS * 4)

// Scratch (no cudaMalloc allowed): residual buffer, per-stage loss accumulators, codeword norms.
__device__ float  g_resid[(size_t)N_TOK * DIM];
__device__ double g_loss[QSTG];
__device__ float  g_cnorm[QSTG * KCB];

__device__ __forceinline__ void ffma2(unsigned long long& d,
                                      unsigned long long a,
                                      unsigned long long b) {
    // packed 2-lane fp32 FMA (Blackwell f32x2) — 2x fp32 rate vs FFMA-3reg
    asm("fma.rn.f32x2 %0, %1, %2, %0;" : "+l"(d) : "l"(a), "l"(b));
}

__device__ __forceinline__ float2 unpack2(unsigned long long v) {
    float2 r;
    asm("mov.b64 {%0, %1}, %2;" : "=f"(r.x), "=f"(r.y) : "l"(v));
    return r;
}

// ---------------------------------------------------------------------------
// prep: codeword squared norms (accurate 4-lane partials) + zero loss accums
// ---------------------------------------------------------------------------
__global__ void prep_kernel(const float* __restrict__ cb) {
    int k = blockIdx.x * blockDim.x + threadIdx.x;
    if (k < QSTG * KCB) {
        const float* p = cb + (size_t)k * DIM;
        float s0 = 0.f, s1 = 0.f, s2 = 0.f, s3 = 0.f;
#pragma unroll
        for (int d = 0; d < DIM; d += 4) {
            s0 = __fadd_rn(s0, __fmul_rn(p[d + 0], p[d + 0]));
            s1 = __fadd_rn(s1, __fmul_rn(p[d + 1], p[d + 1]));
            s2 = __fadd_rn(s2, __fmul_rn(p[d + 2], p[d + 2]));
            s3 = __fadd_rn(s3, __fmul_rn(p[d + 3], p[d + 3]));
        }
        g_cnorm[k] = __fadd_rn(__fadd_rn(s0, s1), __fadd_rn(s2, s3));
    }
    if (blockIdx.x == 0 && threadIdx.x < QSTG) g_loss[threadIdx.x] = 0.0;
}

// ---------------------------------------------------------------------------
// stage: argmin over K codewords + residual update + loss, for one VQ stage
// ---------------------------------------------------------------------------
__global__ void __launch_bounds__(NTHREADS, 1)
stage_kernel(const float* __restrict__ x, const float* __restrict__ cb,
             int q, float* __restrict__ out_idx) {
    extern __shared__ float sm[];
    float* sA  = sm;                    // residual tile [TM][DIM]
    float* sB  = sm + TM * DIM;         // codeword chunk [TKC][BPAD]
    float* sCn = sB + TKC * BPAD;       // chunk codeword norms [TKC]
    // reduction overlay (only used after last chunk's compute)
    float* redV = sB;                   // [TM][16]
    int*   redI = (int*)(sB + TM * 16); // [TM][16]
    __shared__ int   finIdx[TM];
    __shared__ float wsum[NTHREADS / 32];

    const int tid  = threadIdx.x;
    const int tokg = tid >> 4;   // 0..15  (8 tokens each)
    const int cwg  = tid & 15;   // 0..15  (8 strided codewords each)
    const int n0   = blockIdx.x * TM;

    const float* rin = (q == 0) ? x : (const float*)g_resid;
    const float* cbq = cb + (size_t)q * KCB * DIM;

    // ---- load residual tile (coalesced float4) ----
    {
        const float4* gin = (const float4*)(rin + (size_t)n0 * DIM);
        float4* sA4 = (float4*)sA;
#pragma unroll
        for (int i = tid; i < TM * DIM / 4; i += NTHREADS) sA4[i] = gin[i];
    }
    __syncthreads();

    // ---- per-token ||r||^2 (4-lane partials, matches jnp.sum closely) ----
    float rn[8];
#pragma unroll
    for (int ti = 0; ti < 8; ++ti) {
        const float* r = sA + (tokg * 8 + ti) * DIM;
        float s0 = 0.f, s1 = 0.f, s2 = 0.f, s3 = 0.f;
#pragma unroll
        for (int d = 0; d < DIM; d += 4) {
            s0 = __fadd_rn(s0, __fmul_rn(r[d + 0], r[d + 0]));
            s1 = __fadd_rn(s1, __fmul_rn(r[d + 1], r[d + 1]));
            s2 = __fadd_rn(s2, __fmul_rn(r[d + 2], r[d + 2]));
            s3 = __fadd_rn(s3, __fmul_rn(r[d + 3], r[d + 3]));
        }
        rn[ti] = __fadd_rn(__fadd_rn(s0, s1), __fadd_rn(s2, s3));
    }

    float bestv[8];
    int   besti[8];
#pragma unroll
    for (int ti = 0; ti < 8; ++ti) { bestv[ti] = 3.4e38f; besti[ti] = 0; }

    for (int ch = 0; ch < NCHUNK; ++ch) {
        const int k0 = ch * TKC;
        __syncthreads();  // protect sB reuse
        // ---- stage codeword chunk into padded SMEM (coalesced reads) ----
        {
            const float4* gb = (const float4*)(cbq + (size_t)k0 * DIM);
#pragma unroll
            for (int i = tid; i < TKC * DIM / 4; i += NTHREADS) {
                int kk = i >> 4, dq = i & 15;
                float4 v = gb[i];
                float2* dst = (float2*)(sB + kk * BPAD + dq * 4);
                dst[0] = make_float2(v.x, v.y);
                dst[1] = make_float2(v.z, v.w);
            }
            if (tid < TKC) sCn[tid] = g_cnorm[q * KCB + k0 + tid];
        }
        __syncthreads();

        // ---- 8x8 register-tile dot products, d paired for f32x2 ----
        unsigned long long acc[64];
#pragma unroll
        for (int c = 0; c < 64; ++c) acc[c] = 0ull;

        const float* aBase = sA + tokg * 8 * DIM;
        const float* bBase = sB + cwg * BPAD;  // k = cwg + 16*j
#pragma unroll 4
        for (int d2 = 0; d2 < DIM / 2; ++d2) {
            unsigned long long a2[8], b2[8];
#pragma unroll
            for (int ti = 0; ti < 8; ++ti)
                a2[ti] = *(const unsigned long long*)(aBase + ti * DIM + 2 * d2);
#pragma unroll
            for (int j = 0; j < 8; ++j)
                b2[j] = *(const unsigned long long*)(bBase + j * 16 * BPAD + 2 * d2);
#pragma unroll
            for (int ti = 0; ti < 8; ++ti)
#pragma unroll
                for (int j = 0; j < 8; ++j)
                    ffma2(acc[ti * 8 + j], a2[ti], b2[j]);
        }

        // ---- running argmin: val = (rnorm - 2*dot) + cnorm (no contraction) ----
#pragma unroll
        for (int j = 0; j < 8; ++j) {
            const int   kl = cwg + 16 * j;
            const float cn = sCn[kl];
            const int   kg = k0 + kl;
#pragma unroll
            for (int ti = 0; ti < 8; ++ti) {
                float2 p   = unpack2(acc[ti * 8 + j]);
                float  dot = __fadd_rn(p.x, p.y);
                float  val = __fadd_rn(__fsub_rn(rn[ti], __fmul_rn(2.0f, dot)), cn);
                if (val < bestv[ti]) { bestv[ti] = val; besti[ti] = kg; }
            }
        }
    }
    __syncthreads();

    // ---- cross-thread reduction (16 partials per token), first-min tiebreak ----
#pragma unroll
    for (int ti = 0; ti < 8; ++ti) {
        int t = tokg * 8 + ti;
        redV[t * 16 + cwg] = bestv[ti];
        redI[t * 16 + cwg] = besti[ti];
    }
    __syncthreads();
    if (tid < TM) {
        float bv = redV[tid * 16];
        int   bi = redI[tid * 16];
#pragma unroll
        for (int g = 1; g < 16; ++g) {
            float v  = redV[tid * 16 + g];
            int   ii = redI[tid * 16 + g];
            if (v < bv || (v == bv && ii < bi)) { bv = v; bi = ii; }
        }
        finIdx[tid] = bi;
        out_idx[(size_t)(n0 + tid) * QSTG + q] = (float)bi;
    }
    __syncthreads();

    // ---- residual update + loss (2 threads per token, 32 dims each) ----
    {
        const int t = tid >> 1, h = tid & 1;
        const int idx = finIdx[t];
        const float4* c4 = (const float4*)(cbq + (size_t)idx * DIM + h * 32);
        const float4* r4 = (const float4*)(sA + t * DIM + h * 32);
        float4* o4 = (float4*)(g_resid + (size_t)(n0 + t) * DIM + h * 32);
        float ls = 0.f;
#pragma unroll
        for (int m = 0; m < 8; ++m) {
            float4 rv = r4[m], cv = c4[m], nv;
            nv.x = __fsub_rn(rv.x, cv.x);
            nv.y = __fsub_rn(rv.y, cv.y);
            nv.z = __fsub_rn(rv.z, cv.z);
            nv.w = __fsub_rn(rv.w, cv.w);
            o4[m] = nv;
            ls = fmaf(nv.x, nv.x, ls);
            ls = fmaf(nv.y, nv.y, ls);
            ls = fmaf(nv.z, nv.z, ls);
            ls = fmaf(nv.w, nv.w, ls);
        }
#pragma unroll
        for (int off = 16; off; off >>= 1)
            ls += __shfl_down_sync(0xffffffff, ls, off);
        if ((tid & 31) == 0) wsum[tid >> 5] = ls;
        __syncthreads();
        if (tid == 0) {
            float tot = 0.f;
#pragma unroll
            for (int w = 0; w < NTHREADS / 32; ++w) tot += wsum[w];
            atomicAdd(&g_loss[q], (double)tot);
        }
    }
}

// ---------------------------------------------------------------------------
// finalize: xq = x - residual_final ; losses = g_loss / (N*D)
// ---------------------------------------------------------------------------
__global__ void final_kernel(const float* __restrict__ x, float* __restrict__ out) {
    size_t i = (size_t)blockIdx.x * blockDim.x + threadIdx.x;
    if (i < (size_t)N_TOK * DIM / 4) {
        const float4* x4 = (const float4*)x;
        const float4* r4 = (const float4*)g_resid;
        float4* o4 = (float4*)out;
        float4 xv = x4[i], rv = r4[i], ov;
        ov.x = __fsub_rn(xv.x, rv.x);
        ov.y = __fsub_rn(xv.y, rv.y);
        ov.z = __fsub_rn(xv.z, rv.z);
        ov.w = __fsub_rn(xv.w, rv.w);
        o4[i] = ov;
    }
    if (blockIdx.x == 0 && threadIdx.x < QSTG) {
        out[(size_t)N_TOK * DIM + (size_t)N_TOK * QSTG + threadIdx.x] =
            (float)(g_loss[threadIdx.x] / (double)((size_t)N_TOK * DIM));
    }
}

extern "C" void kernel_launch(void* const* d_in, const int* in_sizes, int n_in,
                              void* d_out, int out_size) {
    const float* x  = (const float*)d_in[0];
    const float* cb = (const float*)d_in[1];
    // defensive: if metadata order is (codebooks, x), swap
    if (n_in >= 2 && in_sizes[0] == QSTG * KCB * DIM && in_sizes[1] == N_TOK * DIM) {
        const float* t = x; x = cb; cb = t;
    }
    float* out     = (float*)d_out;
    float* out_idx = out + (size_t)N_TOK * DIM;

    cudaFuncSetAttribute(stage_kernel,
                         cudaFuncAttributeMaxDynamicSharedMemorySize, SMEM_BYTES);

    prep_kernel<<<(QSTG * KCB + 255) / 256, 256>>>(cb);
    for (int q = 0; q < QSTG; ++q)
        stage_kernel<<<N_TOK / TM, NTHREADS, SMEM_BYTES>>>(x, cb, q, out_idx);
    final_kernel<<<(N_TOK * DIM / 4 + 255) / 256, 256>>>(x, out);
}

// round 2
// speedup vs baseline: 1.2820x; 1.2820x over previous
#include <cuda_runtime.h>
#include <cstdint>

#define N_TOK 131072
#define DIM   64
#define QSTG  8
#define KCB   1024

#define TM       128            // tokens per CTA
#define TKC      256            // codewords per SMEM chunk
#define NCHUNK   (KCB / TKC)    // 4
#define NTHREADS 256

typedef unsigned long long ull;

// dynamic smem layout (floats):
//   sA   [TM][DIM]                 : 8192
//   sBt  64 rows x 1024 B (pairs)  : 16384   (row d holds 128 pairs (B[2k][d],B[2k+1][d]), slot = k ^ (d>>2))
//   sCn  [TKC]                     : 256
#define SA_F    0
#define SBT_F   (TM * DIM)                  // 8192
#define SCN_F   (SBT_F + 64 * 256)          // 8192 + 16384
#define SMEM_FLOATS (SCN_F + TKC)
#define SMEM_BYTES  (SMEM_FLOATS * 4)

__device__ double g_loss[QSTG];
__device__ float  g_cnorm[QSTG * KCB];

__device__ __forceinline__ void ffma2(ull& d, ull a, ull b) {
    asm("fma.rn.f32x2 %0, %1, %2, %0;" : "+l"(d) : "l"(a), "l"(b));
}
__device__ __forceinline__ ull dup2(float a) {
    ull r; unsigned u = __float_as_uint(a);
    asm("mov.b64 %0, {%1, %1};" : "=l"(r) : "r"(u));
    return r;
}
__device__ __forceinline__ float2 unpack2(ull v) {
    float2 r;
    asm("mov.b64 {%0, %1}, %2;" : "=f"(r.x), "=f"(r.y) : "l"(v));
    return r;
}

// ---------------------------------------------------------------------------
// prep: codeword squared norms + zero loss accumulators
// ---------------------------------------------------------------------------
__global__ void prep_kernel(const float* __restrict__ cb) {
    int k = blockIdx.x * blockDim.x + threadIdx.x;
    if (k < QSTG * KCB) {
        const float* p = cb + (size_t)k * DIM;
        float s0 = 0.f, s1 = 0.f, s2 = 0.f, s3 = 0.f;
#pragma unroll
        for (int d = 0; d < DIM; d += 4) {
            s0 = __fadd_rn(s0, __fmul_rn(p[d + 0], p[d + 0]));
            s1 = __fadd_rn(s1, __fmul_rn(p[d + 1], p[d + 1]));
            s2 = __fadd_rn(s2, __fmul_rn(p[d + 2], p[d + 2]));
            s3 = __fadd_rn(s3, __fmul_rn(p[d + 3], p[d + 3]));
        }
        g_cnorm[k] = __fadd_rn(__fadd_rn(s0, s1), __fadd_rn(s2, s3));
    }
    if (blockIdx.x == 0 && threadIdx.x < QSTG) g_loss[threadIdx.x] = 0.0;
}

// ---------------------------------------------------------------------------
// fused: all 8 VQ stages for one 128-token tile (residual stays in SMEM)
// ---------------------------------------------------------------------------
__global__ void __launch_bounds__(NTHREADS, 1)
vq_kernel(const float* __restrict__ x, const float* __restrict__ cb,
          float* __restrict__ out) {
    extern __shared__ float sm[];
    float* sA  = sm + SA_F;
    float* sBt = sm + SBT_F;
    float* sCn = sm + SCN_F;
    // reduction overlay (reuses sBt region between chunk phases)
    float* redV = sBt;                        // [TM][16]
    int*   redI = (int*)(sBt + TM * 16);      // [TM][16]
    __shared__ int   finIdx[TM];
    __shared__ float wsum[NTHREADS / 32];

    const int tid  = threadIdx.x;
    const int tokg = tid >> 4;    // 0..15 : 8 tokens each
    const int cwg  = tid & 15;    // 0..15 : 8 codeword-pairs per chunk
    const int n0   = blockIdx.x * TM;

    float* out_xq  = out;
    float* out_idx = out + (size_t)N_TOK * DIM;

    // ---- load token tile once ----
    {
        const float4* gin = (const float4*)(x + (size_t)n0 * DIM);
        float4* sA4 = (float4*)sA;
#pragma unroll
        for (int i = tid; i < TM * DIM / 4; i += NTHREADS) sA4[i] = gin[i];
    }

    for (int q = 0; q < QSTG; ++q) {
        const float* cbq = cb + (size_t)q * KCB * DIM;

        float bestv[8];
        int   besti[8];
#pragma unroll
        for (int ti = 0; ti < 8; ++ti) { bestv[ti] = 3.4e38f; besti[ti] = 0; }

        for (int ch = 0; ch < NCHUNK; ++ch) {
            const int k0 = ch * TKC;
            __syncthreads();   // previous users of sBt / sA writers done

            // ---- stage B chunk as transposed pairs, swizzled slot = p ^ (d>>2) ----
            {
                const float4* gb = (const float4*)(cbq + (size_t)k0 * DIM);
#pragma unroll
                for (int it = 0; it < 8; ++it) {
                    int L = it * NTHREADS + tid;       // 0..2047
                    int p  = L >> 4;                   // pair index 0..127
                    int dq = L & 15;                   // d quad 0..15
                    float4 v1 = gb[(2 * p) * 16 + dq];
                    float4 v2 = gb[(2 * p + 1) * 16 + dq];
                    const float* a1 = &v1.x;
                    const float* a2 = &v2.x;
                    int swz = p ^ dq;
#pragma unroll
                    for (int m = 0; m < 4; ++m) {
                        float2* dst = (float2*)((char*)sBt + (size_t)(4 * dq + m) * 1024) + swz;
                        *dst = make_float2(a1[m], a2[m]);
                    }
                }
                sCn[tid] = g_cnorm[q * KCB + k0 + tid];
            }
            __syncthreads();

            // ---- 8 tokens x 8 codeword-pairs register tile ----
            ull acc[64];
#pragma unroll
            for (int c = 0; c < 64; ++c) acc[c] = 0ull;

            const float* aTok = sA + tokg * 8 * DIM;
#pragma unroll 4
            for (int d = 0; d < DIM; ++d) {
                ull a2r[8];
#pragma unroll
                for (int ti = 0; ti < 8; ++ti)
                    a2r[ti] = dup2(aTok[ti * DIM + d]);
                const ull* bRow = (const ull*)((char*)sBt + (size_t)d * 1024) + (cwg ^ (d >> 2));
                ull b2r[8];
#pragma unroll
                for (int j = 0; j < 8; ++j) b2r[j] = bRow[16 * j];
#pragma unroll
                for (int ti = 0; ti < 8; ++ti)
#pragma unroll
                    for (int j = 0; j < 8; ++j)
                        ffma2(acc[ti * 8 + j], a2r[ti], b2r[j]);
            }

            // ---- running argmin: val = cnorm - 2*dot  (rnorm is a per-token constant) ----
#pragma unroll
            for (int j = 0; j < 8; ++j) {
                const int kl = 2 * (cwg + 16 * j);
                const float2 cn = *(const float2*)(sCn + kl);
                const int kg = k0 + kl;
#pragma unroll
                for (int ti = 0; ti < 8; ++ti) {
                    float2 p = unpack2(acc[ti * 8 + j]);
                    float v0 = fmaf(-2.0f, p.x, cn.x);
                    float v1 = fmaf(-2.0f, p.y, cn.y);
                    bool l0 = v0 < bestv[ti];
                    bestv[ti] = l0 ? v0 : bestv[ti];
                    besti[ti] = l0 ? kg : besti[ti];
                    bool l1 = v1 < bestv[ti];
                    bestv[ti] = l1 ? v1 : bestv[ti];
                    besti[ti] = l1 ? (kg + 1) : besti[ti];
                }
            }
        }
        __syncthreads();

        // ---- cross-thread argmin (16 partials per token), index tiebreak ----
#pragma unroll
        for (int ti = 0; ti < 8; ++ti) {
            int t = tokg * 8 + ti;
            redV[t * 16 + cwg] = bestv[ti];
            redI[t * 16 + cwg] = besti[ti];
        }
        __syncthreads();
        if (tid < TM) {
            float bv = redV[tid * 16];
            int   bi = redI[tid * 16];
#pragma unroll
            for (int g = 1; g < 16; ++g) {
                float v  = redV[tid * 16 + g];
                int   ii = redI[tid * 16 + g];
                if (v < bv || (v == bv && ii < bi)) { bv = v; bi = ii; }
            }
            finIdx[tid] = bi;
            out_idx[(size_t)(n0 + tid) * QSTG + q] = (float)bi;
        }
        __syncthreads();

        // ---- residual update (in SMEM) + commitment loss ----
        {
            const int t = tid >> 1, h = tid & 1;
            const int idx = finIdx[t];
            const float4* c4 = (const float4*)(cbq + (size_t)idx * DIM + h * 32);
            float4* r4 = (float4*)(sA + t * DIM + h * 32);
            float ls = 0.f;
#pragma unroll
            for (int m = 0; m < 8; ++m) {
                float4 rv = r4[m], cv = c4[m], nv;
                nv.x = __fsub_rn(rv.x, cv.x);
                nv.y = __fsub_rn(rv.y, cv.y);
                nv.z = __fsub_rn(rv.z, cv.z);
                nv.w = __fsub_rn(rv.w, cv.w);
                r4[m] = nv;
                ls = fmaf(nv.x, nv.x, ls);
                ls = fmaf(nv.y, nv.y, ls);
                ls = fmaf(nv.z, nv.z, ls);
                ls = fmaf(nv.w, nv.w, ls);
            }
#pragma unroll
            for (int off = 16; off; off >>= 1)
                ls += __shfl_down_sync(0xffffffff, ls, off);
            if ((tid & 31) == 0) wsum[tid >> 5] = ls;
            __syncthreads();
            if (tid == 0) {
                float tot = 0.f;
#pragma unroll
                for (int w = 0; w < NTHREADS / 32; ++w) tot += wsum[w];
                atomicAdd(&g_loss[q], (double)tot);
            }
        }
    }
    __syncthreads();

    // ---- xq = x - final_residual ----
    {
        const float4* x4 = (const float4*)(x + (size_t)n0 * DIM);
        const float4* r4 = (const float4*)sA;
        float4* o4 = (float4*)(out_xq + (size_t)n0 * DIM);
#pragma unroll
        for (int i = tid; i < TM * DIM / 4; i += NTHREADS) {
            float4 xv = x4[i], rv = r4[i], ov;
            ov.x = __fsub_rn(xv.x, rv.x);
            ov.y = __fsub_rn(xv.y, rv.y);
            ov.z = __fsub_rn(xv.z, rv.z);
            ov.w = __fsub_rn(xv.w, rv.w);
            o4[i] = ov;
        }
    }
}

// ---------------------------------------------------------------------------
// losses
// ---------------------------------------------------------------------------
__global__ void loss_kernel(float* __restrict__ out) {
    if (threadIdx.x < QSTG)
        out[(size_t)N_TOK * DIM + (size_t)N_TOK * QSTG + threadIdx.x] =
            (float)(g_loss[threadIdx.x] / (double)((size_t)N_TOK * DIM));
}

extern "C" void kernel_launch(void* const* d_in, const int* in_sizes, int n_in,
                              void* d_out, int out_size) {
    const float* x  = (const float*)d_in[0];
    const float* cb = (const float*)d_in[1];
    if (n_in >= 2 && in_sizes[0] == QSTG * KCB * DIM && in_sizes[1] == N_TOK * DIM) {
        const float* t = x; x = cb; cb = t;
    }
    float* out = (float*)d_out;

    cudaFuncSetAttribute(vq_kernel,
                         cudaFuncAttributeMaxDynamicSharedMemorySize, SMEM_BYTES);

    prep_kernel<<<(QSTG * KCB + 255) / 256, 256>>>(cb);
    vq_kernel<<<N_TOK / TM, NTHREADS, SMEM_BYTES>>>(x, cb, out);
    loss_kernel<<<1, 32>>>(out);
}